// round 6
// baseline (speedup 1.0000x reference)
#include <cuda_runtime.h>
#include <cuda_fp16.h>
#include <cstdint>

#define NS     25
#define NQ     200
#define NITEM  (NS + NQ)        // 225
#define FF     80
#define DD     512
#define WAY    5
#define BLK    128
#define NBLK   10               // packed upper-tri 128x128 blocks of 4x4 grid
#define BLKSZ  (BLK * BLK)      // 16384 halves per block
#define KPACK  (NBLK * BLKSZ)   // 163840
#define PITCH  136              // smem pitch (halves) for X slices

// -------- scratch (__device__ globals; no allocations allowed) --------------
__device__ __half g_Sn[NS * FF * DD];        // 2 MB   normalized supports
__device__ __half g_Qn[NQ * FF * DD];        // 16.4MB normalized queries
__device__ float  g_bar[NITEM][DD];          // per-item feature-row sums
__device__ float  g_sbarsum[WAY][DD];        // class-summed support row-sums
__device__ int    g_cls_cnt[WAY];
__device__ int    g_cls_sup[WAY][NS];
__device__ __half g_Gc[WAY][KPACK];          // class Grams, FRAGMENT ORDER, x2 offdiag
__device__ float  g_S2[WAY][NQ];

__constant__ int c_bi[NBLK] = {0,0,0,0,1,1,1,2,2,3};
__constant__ int c_bj[NBLK] = {0,1,2,3,1,2,3,2,3,3};

// ---------------------------------------------------------------------------
// K1: L2-normalize each D=512 feature row (proven)
// ---------------------------------------------------------------------------
__global__ void normalize_kernel(const float* __restrict__ sg, const float* __restrict__ sl,
                                 const float* __restrict__ qg, const float* __restrict__ ql)
{
    int warp = (blockIdx.x * blockDim.x + threadIdx.x) >> 5;
    int lane = threadIdx.x & 31;
    if (warp >= NITEM * FF) return;

    const float* src;
    __half* dst;
    if (warp < NS * FF) {
        int s = warp / FF, f = warp % FF;
        src = (f < 16) ? sg + (size_t)(s * 16 + f) * DD
                       : sl + (size_t)(s * 64 + (f - 16)) * DD;
        dst = g_Sn + (size_t)warp * DD;
    } else {
        int r = warp - NS * FF;
        int q = r / FF, f = r % FF;
        src = (f < 16) ? qg + (size_t)(q * 16 + f) * DD
                       : ql + (size_t)(q * 64 + (f - 16)) * DD;
        dst = g_Qn + (size_t)r * DD;
    }

    float4 v[4];
    float ss = 0.f;
    const float4* s4 = reinterpret_cast<const float4*>(src);
#pragma unroll
    for (int i = 0; i < 4; i++) {
        v[i] = s4[lane + 32 * i];
        ss += v[i].x * v[i].x + v[i].y * v[i].y + v[i].z * v[i].z + v[i].w * v[i].w;
    }
#pragma unroll
    for (int o = 16; o; o >>= 1) ss += __shfl_xor_sync(0xFFFFFFFFu, ss, o);
    float rn = rsqrtf(fmaxf(ss, 1e-24f));

    __half2* d2 = reinterpret_cast<__half2*>(dst);
#pragma unroll
    for (int i = 0; i < 4; i++) {
        d2[2 * (lane + 32 * i) + 0] = __floats2half2_rn(v[i].x * rn, v[i].y * rn);
        d2[2 * (lane + 32 * i) + 1] = __floats2half2_rn(v[i].z * rn, v[i].w * rn);
    }
}

// ---------------------------------------------------------------------------
// K2: per-item feature-row sums (proven)
// ---------------------------------------------------------------------------
__global__ void rowsum_kernel()
{
    int item = blockIdx.x;
    int t = threadIdx.x;
    const __half2* X = reinterpret_cast<const __half2*>(
        (item < NS) ? g_Sn + (size_t)item * FF * DD
                    : g_Qn + (size_t)(item - NS) * FF * DD);
    float sx = 0.f, sy = 0.f;
#pragma unroll 8
    for (int f = 0; f < FF; f++) {
        float2 v = __half22float2(X[f * (DD / 2) + t]);
        sx += v.x; sy += v.y;
    }
    g_bar[item][2 * t + 0] = sx;
    g_bar[item][2 * t + 1] = sy;
}

// ---------------------------------------------------------------------------
// K3: class lists, class-summed row-sums, zero S2 (proven)
// ---------------------------------------------------------------------------
__global__ void prep_kernel(const long long* __restrict__ labels)
{
    __shared__ int cnt[WAY];
    __shared__ int sup[WAY][NS];
    int t = threadIdx.x;  // 512
    if (t == 0) {
        for (int c = 0; c < WAY; c++) cnt[c] = 0;
        for (int s = 0; s < NS; s++) {
            int c = (int)labels[s];
            sup[c][cnt[c]++] = s;
        }
        for (int c = 0; c < WAY; c++) {
            g_cls_cnt[c] = cnt[c];
            for (int i = 0; i < cnt[c]; i++) g_cls_sup[c][i] = sup[c][i];
        }
    }
    __syncthreads();
    if (t < DD) {
#pragma unroll
        for (int c = 0; c < WAY; c++) {
            float a = 0.f;
            for (int i = 0; i < cnt[c]; i++) a += g_bar[sup[c][i]][t];
            g_sbarsum[c][t] = a;
        }
    }
    for (int i = t; i < WAY * NQ; i += blockDim.x)
        (&g_S2[0][0])[i] = 0.f;
}

// ---------------------------------------------------------------------------
// shared mma machinery
// ---------------------------------------------------------------------------
__device__ __forceinline__ void ldsm_x4_t(uint32_t (&r)[4], const __half* p)
{
    uint32_t a = (uint32_t)__cvta_generic_to_shared(p);
    asm volatile("ldmatrix.sync.aligned.m8n8.x4.trans.shared.b16 {%0,%1,%2,%3}, [%4];"
                 : "=r"(r[0]), "=r"(r[1]), "=r"(r[2]), "=r"(r[3]) : "r"(a));
}

__device__ __forceinline__ void mma16816(float (&d)[4], const uint32_t (&a)[4],
                                         uint32_t b0, uint32_t b1)
{
    asm volatile("mma.sync.aligned.m16n8k16.row.col.f32.f16.f16.f32 "
                 "{%0,%1,%2,%3},{%4,%5,%6,%7},{%8,%9},{%0,%1,%2,%3};"
                 : "+f"(d[0]), "+f"(d[1]), "+f"(d[2]), "+f"(d[3])
                 : "r"(a[0]), "r"(a[1]), "r"(a[2]), "r"(a[3]), "r"(b0), "r"(b1));
}

// Compute one 128x128 Gram block (X_bi^T X_bj) into acc[2][8][4].
// Tiles must already be in sX0 (bi slice) / sX1 (bj slice or alias sX0 if diag).
__device__ __forceinline__ void gram_block_mma(
    const __half* sX0, const __half* pB, float (&acc)[2][8][4],
    int m_base, int n_base, int lane)
{
    const int a_krow = ((lane >> 4) << 3) + (lane & 7);
    const int a_coff = ((lane >> 3) & 1) << 3;
    const int b_krow = (((lane >> 3) & 1) << 3) + (lane & 7);
    const int b_coff = (lane >> 4) << 3;

#pragma unroll
    for (int k16 = 0; k16 < FF / 16; k16++) {
        const int k0 = k16 * 16;
        uint32_t a[2][4];
#pragma unroll
        for (int mt = 0; mt < 2; mt++)
            ldsm_x4_t(a[mt], &sX0[(k0 + a_krow) * PITCH + m_base + mt * 16 + a_coff]);
#pragma unroll
        for (int nt = 0; nt < 4; nt++) {
            uint32_t bf[4];
            ldsm_x4_t(bf, &pB[(k0 + b_krow) * PITCH + n_base + nt * 16 + b_coff]);
#pragma unroll
            for (int mt = 0; mt < 2; mt++) {
                mma16816(acc[mt][2 * nt + 0], a[mt], bf[0], bf[1]);
                mma16816(acc[mt][2 * nt + 1], a[mt], bf[2], bf[3]);
            }
        }
    }
}

extern __shared__ char dynsmem[];

// ---------------------------------------------------------------------------
// K4: class-summed support Gram blocks -> g_Gc in FRAGMENT ORDER.
// grid (NBLK, WAY). Each thread writes its 64 fragment values contiguously
// at [b*BLKSZ + tid*64]  (x2 scale on off-diagonal blocks).
// ---------------------------------------------------------------------------
__global__ void __launch_bounds__(256, 2) sgram_kernel()
{
    __half* sX0 = (__half*)dynsmem;
    __half* sX1 = sX0 + FF * PITCH;

    const int b = blockIdx.x;
    const int c = blockIdx.y;
    const int bi = c_bi[b], bj = c_bj[b];
    const bool diag = (bi == bj);

    const int tid  = threadIdx.x;
    const int lane = tid & 31;
    const int warp = tid >> 5;
    const int m_base = (warp >> 1) * 32;
    const int n_base = (warp & 1) * 64;

    float acc[2][8][4];
#pragma unroll
    for (int mt = 0; mt < 2; mt++)
#pragma unroll
        for (int nt = 0; nt < 8; nt++)
#pragma unroll
            for (int i = 0; i < 4; i++) acc[mt][nt][i] = 0.f;

    const int nsup = g_cls_cnt[c];
    const __half* pB = diag ? sX0 : sX1;
    const int nch = diag ? 1280 : 2560;

    for (int si = 0; si < nsup; si++) {
        const __half* base = g_Sn + (size_t)g_cls_sup[c][si] * FF * DD;
        for (int ch = tid; ch < nch; ch += 256) {
            int tile = (ch >= 1280) ? 1 : 0;
            int rem  = ch - tile * 1280;
            int r = rem >> 4, cc = rem & 15;
            int colblk = tile ? bj : bi;
            const __half* src = base + (size_t)r * DD + colblk * 128 + cc * 8;
            __half* dsts = (tile ? sX1 : sX0) + r * PITCH + cc * 8;
            uint32_t dst = (uint32_t)__cvta_generic_to_shared(dsts);
            asm volatile("cp.async.cg.shared.global [%0], [%1], 16;" :: "r"(dst), "l"(src));
        }
        asm volatile("cp.async.commit_group;");
        asm volatile("cp.async.wait_group 0;");
        __syncthreads();

        gram_block_mma(sX0, pB, acc, m_base, n_base, lane);
        __syncthreads();
    }

    // fragment-order coalesced-dense output: 64 halves per thread = 8 int4
    const float scale = diag ? 1.f : 2.f;
    __half outv[64];
#pragma unroll
    for (int mt = 0; mt < 2; mt++)
#pragma unroll
        for (int nt = 0; nt < 8; nt++)
#pragma unroll
            for (int i = 0; i < 4; i++)
                outv[mt * 32 + nt * 4 + i] = __float2half_rn(acc[mt][nt][i] * scale);

    __half* out = g_Gc[c] + (size_t)b * BLKSZ + tid * 64;
#pragma unroll
    for (int j = 0; j < 8; j++)
        *(int4*)(out + j * 8) = *(const int4*)&outv[j * 8];
}

// ---------------------------------------------------------------------------
// K5: fused query Gram + Frobenius dot. grid (NBLK, NQ) = 2000 CTAs.
// H block stays in registers; each thread dots its 64 fragment values against
// the matching Gc slice (L2-resident, contiguous per thread) for all 5 classes.
// ---------------------------------------------------------------------------
__global__ void __launch_bounds__(256, 2) qdot_kernel()
{
    __half* sX0 = (__half*)dynsmem;
    __half* sX1 = sX0 + FF * PITCH;

    const int b = blockIdx.x;
    const int q = blockIdx.y;
    const int bi = c_bi[b], bj = c_bj[b];
    const bool diag = (bi == bj);

    const int tid  = threadIdx.x;
    const int lane = tid & 31;
    const int warp = tid >> 5;
    const int m_base = (warp >> 1) * 32;
    const int n_base = (warp & 1) * 64;

    float acc[2][8][4];
#pragma unroll
    for (int mt = 0; mt < 2; mt++)
#pragma unroll
        for (int nt = 0; nt < 8; nt++)
#pragma unroll
            for (int i = 0; i < 4; i++) acc[mt][nt][i] = 0.f;

    const __half* base = g_Qn + (size_t)q * FF * DD;
    const __half* pB = diag ? sX0 : sX1;
    const int nch = diag ? 1280 : 2560;

    for (int ch = tid; ch < nch; ch += 256) {
        int tile = (ch >= 1280) ? 1 : 0;
        int rem  = ch - tile * 1280;
        int r = rem >> 4, cc = rem & 15;
        int colblk = tile ? bj : bi;
        const __half* src = base + (size_t)r * DD + colblk * 128 + cc * 8;
        __half* dsts = (tile ? sX1 : sX0) + r * PITCH + cc * 8;
        uint32_t dst = (uint32_t)__cvta_generic_to_shared(dsts);
        asm volatile("cp.async.cg.shared.global [%0], [%1], 16;" :: "r"(dst), "l"(src));
    }
    asm volatile("cp.async.commit_group;");
    asm volatile("cp.async.wait_group 0;");
    __syncthreads();

    gram_block_mma(sX0, pB, acc, m_base, n_base, lane);

    // flatten acc in fragment order
    float av[64];
#pragma unroll
    for (int mt = 0; mt < 2; mt++)
#pragma unroll
        for (int nt = 0; nt < 8; nt++)
#pragma unroll
            for (int i = 0; i < 4; i++)
                av[mt * 32 + nt * 4 + i] = acc[mt][nt][i];

    // in-register Frobenius dot vs all 5 class Grams (fragment-matched slices)
    float part[WAY];
#pragma unroll
    for (int c = 0; c < WAY; c++) {
        const __half* Gp = g_Gc[c] + (size_t)b * BLKSZ + tid * 64;
        float p = 0.f;
#pragma unroll
        for (int j = 0; j < 8; j++) {
            int4 gv = *(const int4*)(Gp + j * 8);
            const __half2* gh = (const __half2*)&gv;
#pragma unroll
            for (int k = 0; k < 4; k++) {
                float2 gf = __half22float2(gh[k]);
                p += av[j * 8 + 2 * k] * gf.x + av[j * 8 + 2 * k + 1] * gf.y;
            }
        }
        part[c] = p;
    }

#pragma unroll
    for (int o = 16; o; o >>= 1)
#pragma unroll
        for (int c = 0; c < WAY; c++)
            part[c] += __shfl_xor_sync(0xFFFFFFFFu, part[c], o);

    __shared__ float red[8][WAY];
    if (lane == 0)
#pragma unroll
        for (int c = 0; c < WAY; c++) red[warp][c] = part[c];
    __syncthreads();
    if (tid < WAY) {
        float s = 0.f;
#pragma unroll
        for (int w = 0; w < 8; w++) s += red[w][tid];
        atomicAdd(&g_S2[tid][q], s);
    }
}

// ---------------------------------------------------------------------------
// K6: logits (proven)
// ---------------------------------------------------------------------------
__global__ void logits_kernel(float* __restrict__ out)
{
    int warp = (blockIdx.x * blockDim.x + threadIdx.x) >> 5;
    int lane = threadIdx.x & 31;
    if (warp >= NQ) return;
    const int q = warp;

    float s1[WAY] = {0.f, 0.f, 0.f, 0.f, 0.f};
    const float* qb = g_bar[NS + q];
    for (int k = lane; k < DD; k += 32) {
        float qv = qb[k];
#pragma unroll
        for (int c = 0; c < WAY; c++) s1[c] += g_sbarsum[c][k] * qv;
    }
#pragma unroll
    for (int o = 16; o; o >>= 1)
#pragma unroll
        for (int c = 0; c < WAY; c++)
            s1[c] += __shfl_xor_sync(0xFFFFFFFFu, s1[c], o);

    if (lane < WAY) {
        int c = lane;
        float cnt = (float)g_cls_cnt[c];
        out[q * WAY + c] = -2.f * (float)(FF * FF) + (4.f * s1[c] - 2.f * g_S2[c][q]) / cnt;
    }
}

// ---------------------------------------------------------------------------
extern "C" void kernel_launch(void* const* d_in, const int* in_sizes, int n_in,
                              void* d_out, int out_size)
{
    const float*     sg  = (const float*)d_in[0];
    const float*     sl  = (const float*)d_in[1];
    const long long* lab = (const long long*)d_in[2];
    const float*     qg  = (const float*)d_in[3];
    const float*     ql  = (const float*)d_in[4];
    float*           out = (float*)d_out;

    const int smem = 2 * FF * PITCH * 2;   // 43520 B (< 48KB, no attribute needed)

    const int rows = NITEM * FF;
    normalize_kernel<<<(rows * 32 + 255) / 256, 256>>>(sg, sl, qg, ql);
    rowsum_kernel<<<NITEM, 256>>>();
    prep_kernel<<<1, 512>>>(lab);
    sgram_kernel<<<dim3(NBLK, WAY), 256, smem>>>();    // 50 CTAs
    qdot_kernel<<<dim3(NBLK, NQ), 256, smem>>>();      // 2000 CTAs
    logits_kernel<<<(NQ * 32 + 255) / 256, 256>>>(out);
}

// round 7
// speedup vs baseline: 2.4505x; 2.4505x over previous
#include <cuda_runtime.h>
#include <cuda_fp16.h>
#include <cstdint>

#define NS     25
#define NQ     200
#define NITEM  (NS + NQ)        // 225
#define FF     80
#define DD     512
#define WAY    5
#define BLK    128
#define NBLK   10               // packed upper-tri 128x128 blocks of 4x4 grid
#define BLKSZ  (BLK * BLK)      // 16384 halves per block
#define KPACK  (NBLK * BLKSZ)   // 163840
#define PITCH  136              // smem pitch (halves) for X slices
#define SLICE  (FF * PITCH)     // halves per slice buffer
#define NUNIT  (NBLK * NITEM)   // 2250
#define GGRID  296              // persistent CTAs (2/SM)

// -------- scratch (__device__ globals; no allocations allowed) --------------
__device__ __half g_Sn[NS * FF * DD];        // 2 MB   normalized supports
__device__ __half g_Qn[NQ * FF * DD];        // 16.4MB normalized queries
__device__ __half g_Gs[NS][KPACK];           // per-support Grams, frag order (x2 offdiag)
__device__ __half g_Gc[WAY][KPACK];          // class-summed Grams, frag order
__device__ __half g_Hp[NQ][KPACK];           // query Grams, frag order
__device__ float  g_bar[NITEM][DD];          // per-item feature-row sums
__device__ float  g_sbarsum[WAY][DD];
__device__ int    g_cls_cnt[WAY];
__device__ int    g_cls_sup[WAY][NS];
__device__ float  g_S2[WAY][NQ];

__constant__ int c_bi[NBLK] = {0,0,0,0,1,1,1,2,2,3};
__constant__ int c_bj[NBLK] = {0,1,2,3,1,2,3,2,3,3};

// ---------------------------------------------------------------------------
// K1: L2-normalize each D=512 feature row (proven)
// ---------------------------------------------------------------------------
__global__ void normalize_kernel(const float* __restrict__ sg, const float* __restrict__ sl,
                                 const float* __restrict__ qg, const float* __restrict__ ql)
{
    int warp = (blockIdx.x * blockDim.x + threadIdx.x) >> 5;
    int lane = threadIdx.x & 31;
    if (warp >= NITEM * FF) return;

    const float* src;
    __half* dst;
    if (warp < NS * FF) {
        int s = warp / FF, f = warp % FF;
        src = (f < 16) ? sg + (size_t)(s * 16 + f) * DD
                       : sl + (size_t)(s * 64 + (f - 16)) * DD;
        dst = g_Sn + (size_t)warp * DD;
    } else {
        int r = warp - NS * FF;
        int q = r / FF, f = r % FF;
        src = (f < 16) ? qg + (size_t)(q * 16 + f) * DD
                       : ql + (size_t)(q * 64 + (f - 16)) * DD;
        dst = g_Qn + (size_t)r * DD;
    }

    float4 v[4];
    float ss = 0.f;
    const float4* s4 = reinterpret_cast<const float4*>(src);
#pragma unroll
    for (int i = 0; i < 4; i++) {
        v[i] = s4[lane + 32 * i];
        ss += v[i].x * v[i].x + v[i].y * v[i].y + v[i].z * v[i].z + v[i].w * v[i].w;
    }
#pragma unroll
    for (int o = 16; o; o >>= 1) ss += __shfl_xor_sync(0xFFFFFFFFu, ss, o);
    float rn = rsqrtf(fmaxf(ss, 1e-24f));

    __half2* d2 = reinterpret_cast<__half2*>(dst);
#pragma unroll
    for (int i = 0; i < 4; i++) {
        d2[2 * (lane + 32 * i) + 0] = __floats2half2_rn(v[i].x * rn, v[i].y * rn);
        d2[2 * (lane + 32 * i) + 1] = __floats2half2_rn(v[i].z * rn, v[i].w * rn);
    }
}

// ---------------------------------------------------------------------------
// K2: per-item feature-row sums (proven)
// ---------------------------------------------------------------------------
__global__ void rowsum_kernel()
{
    int item = blockIdx.x;
    int t = threadIdx.x;
    const __half2* X = reinterpret_cast<const __half2*>(
        (item < NS) ? g_Sn + (size_t)item * FF * DD
                    : g_Qn + (size_t)(item - NS) * FF * DD);
    float sx = 0.f, sy = 0.f;
#pragma unroll 8
    for (int f = 0; f < FF; f++) {
        float2 v = __half22float2(X[f * (DD / 2) + t]);
        sx += v.x; sy += v.y;
    }
    g_bar[item][2 * t + 0] = sx;
    g_bar[item][2 * t + 1] = sy;
}

// ---------------------------------------------------------------------------
// K3: class lists, class-summed row-sums, zero S2 (proven)
// ---------------------------------------------------------------------------
__global__ void prep_kernel(const long long* __restrict__ labels)
{
    __shared__ int cnt[WAY];
    __shared__ int sup[WAY][NS];
    int t = threadIdx.x;  // 512
    if (t == 0) {
        for (int c = 0; c < WAY; c++) cnt[c] = 0;
        for (int s = 0; s < NS; s++) {
            int c = (int)labels[s];
            sup[c][cnt[c]++] = s;
        }
        for (int c = 0; c < WAY; c++) {
            g_cls_cnt[c] = cnt[c];
            for (int i = 0; i < cnt[c]; i++) g_cls_sup[c][i] = sup[c][i];
        }
    }
    __syncthreads();
    if (t < DD) {
#pragma unroll
        for (int c = 0; c < WAY; c++) {
            float a = 0.f;
            for (int i = 0; i < cnt[c]; i++) a += g_bar[sup[c][i]][t];
            g_sbarsum[c][t] = a;
        }
    }
    for (int i = t; i < WAY * NQ; i += blockDim.x)
        (&g_S2[0][0])[i] = 0.f;
}

// ---------------------------------------------------------------------------
// shared mma machinery
// ---------------------------------------------------------------------------
__device__ __forceinline__ void ldsm_x4_t(uint32_t (&r)[4], const __half* p)
{
    uint32_t a = (uint32_t)__cvta_generic_to_shared(p);
    asm volatile("ldmatrix.sync.aligned.m8n8.x4.trans.shared.b16 {%0,%1,%2,%3}, [%4];"
                 : "=r"(r[0]), "=r"(r[1]), "=r"(r[2]), "=r"(r[3]) : "r"(a));
}

__device__ __forceinline__ void mma16816(float (&d)[4], const uint32_t (&a)[4],
                                         uint32_t b0, uint32_t b1)
{
    asm volatile("mma.sync.aligned.m16n8k16.row.col.f32.f16.f16.f32 "
                 "{%0,%1,%2,%3},{%4,%5,%6,%7},{%8,%9},{%0,%1,%2,%3};"
                 : "+f"(d[0]), "+f"(d[1]), "+f"(d[2]), "+f"(d[3])
                 : "r"(a[0]), "r"(a[1]), "r"(a[2]), "r"(a[3]), "r"(b0), "r"(b1));
}

__device__ __forceinline__ void gram_block_mma(
    const __half* sX0, const __half* pB, float (&acc)[2][8][4],
    int m_base, int n_base, int lane)
{
    const int a_krow = ((lane >> 4) << 3) + (lane & 7);
    const int a_coff = ((lane >> 3) & 1) << 3;
    const int b_krow = (((lane >> 3) & 1) << 3) + (lane & 7);
    const int b_coff = (lane >> 4) << 3;

#pragma unroll
    for (int k16 = 0; k16 < FF / 16; k16++) {
        const int k0 = k16 * 16;
        uint32_t a[2][4];
#pragma unroll
        for (int mt = 0; mt < 2; mt++)
            ldsm_x4_t(a[mt], &sX0[(k0 + a_krow) * PITCH + m_base + mt * 16 + a_coff]);
#pragma unroll
        for (int nt = 0; nt < 4; nt++) {
            uint32_t bf[4];
            ldsm_x4_t(bf, &pB[(k0 + b_krow) * PITCH + n_base + nt * 16 + b_coff]);
#pragma unroll
            for (int mt = 0; mt < 2; mt++) {
                mma16816(acc[mt][2 * nt + 0], a[mt], bf[0], bf[1]);
                mma16816(acc[mt][2 * nt + 1], a[mt], bf[2], bf[3]);
            }
        }
    }
}

// ---------------------------------------------------------------------------
// K4: persistent pipelined Gram kernel. 2250 units = (item, block).
// 2-stage cp.async pipeline; fragment-order coalesced output (no staging).
// ---------------------------------------------------------------------------
extern __shared__ char dynsmem[];

__device__ __forceinline__ void issue_unit_load(int u, int stage, int tid)
{
    const int item = u / NBLK, b = u % NBLK;
    const int bi = c_bi[b], bj = c_bj[b];
    const __half* base = (item < NS) ? g_Sn + (size_t)item * FF * DD
                                     : g_Qn + (size_t)(item - NS) * FF * DD;
    __half* s0 = (__half*)dynsmem + stage * 2 * SLICE;
    const int nch = (bi == bj) ? 1280 : 2560;
    for (int ch = tid; ch < nch; ch += 256) {
        int tile = (ch >= 1280) ? 1 : 0;
        int rem  = ch - tile * 1280;
        int r = rem >> 4, cc = rem & 15;
        int colblk = tile ? bj : bi;
        const __half* src = base + (size_t)r * DD + colblk * 128 + cc * 8;
        __half* dsts = s0 + tile * SLICE + r * PITCH + cc * 8;
        uint32_t dst = (uint32_t)__cvta_generic_to_shared(dsts);
        asm volatile("cp.async.cg.shared.global [%0], [%1], 16;" :: "r"(dst), "l"(src));
    }
    asm volatile("cp.async.commit_group;");
}

__global__ void __launch_bounds__(256, 2) gram_kernel()
{
    const int tid  = threadIdx.x;
    const int lane = tid & 31;
    const int warp = tid >> 5;
    const int m_base = (warp >> 1) * 32;
    const int n_base = (warp & 1) * 64;

    int u = blockIdx.x;
    if (u >= NUNIT) return;

    issue_unit_load(u, 0, tid);
    int stage = 0;

    for (; u < NUNIT; u += gridDim.x) {
        const int nextu = u + gridDim.x;
        if (nextu < NUNIT) {
            issue_unit_load(nextu, stage ^ 1, tid);
            asm volatile("cp.async.wait_group 1;");
        } else {
            asm volatile("cp.async.wait_group 0;");
        }
        __syncthreads();

        const int item = u / NBLK, b = u % NBLK;
        const bool diag = (c_bi[b] == c_bj[b]);
        const __half* s0 = (const __half*)dynsmem + stage * 2 * SLICE;
        const __half* pB = diag ? s0 : s0 + SLICE;

        float acc[2][8][4];
#pragma unroll
        for (int mt = 0; mt < 2; mt++)
#pragma unroll
            for (int nt = 0; nt < 8; nt++)
#pragma unroll
                for (int i = 0; i < 4; i++) acc[mt][nt][i] = 0.f;

        gram_block_mma(s0, pB, acc, m_base, n_base, lane);

        // fragment-order coalesced epilogue: int4 j at (j*256+tid)*8 halves
        const float scale = (item < NS && !diag) ? 2.f : 1.f;
        __half* out = ((item < NS) ? g_Gs[item] : g_Hp[item - NS]) + (size_t)b * BLKSZ;
#pragma unroll
        for (int j = 0; j < 8; j++) {
            const int mt = j >> 2, nt0 = (j & 3) * 2;
            __half2 h[4];
            h[0] = __floats2half2_rn(acc[mt][nt0][0] * scale, acc[mt][nt0][1] * scale);
            h[1] = __floats2half2_rn(acc[mt][nt0][2] * scale, acc[mt][nt0][3] * scale);
            h[2] = __floats2half2_rn(acc[mt][nt0 + 1][0] * scale, acc[mt][nt0 + 1][1] * scale);
            h[3] = __floats2half2_rn(acc[mt][nt0 + 1][2] * scale, acc[mt][nt0 + 1][3] * scale);
            *(int4*)(out + (size_t)(j * 256 + tid) * 8) = *(int4*)h;
        }
        __syncthreads();   // all reads of this stage done before it is refilled
        stage ^= 1;
    }
}

// ---------------------------------------------------------------------------
// K5: class-sum per-support Grams -> g_Gc (flat, order-agnostic)
// ---------------------------------------------------------------------------
__global__ void __launch_bounds__(256) classsum_kernel()
{
    const int c    = blockIdx.y;
    const int base = blockIdx.x * 2048 + threadIdx.x * 8;
    const int cnt  = g_cls_cnt[c];

    float acc[8];
#pragma unroll
    for (int i = 0; i < 8; i++) acc[i] = 0.f;

    for (int s = 0; s < cnt; s++) {
        int4 v = *(const int4*)&g_Gs[g_cls_sup[c][s]][base];
        const __half2* h = (const __half2*)&v;
#pragma unroll
        for (int j = 0; j < 4; j++) {
            float2 f = __half22float2(h[j]);
            acc[2 * j + 0] += f.x;
            acc[2 * j + 1] += f.y;
        }
    }
    __half2 o[4];
#pragma unroll
    for (int j = 0; j < 4; j++) o[j] = __floats2half2_rn(acc[2 * j], acc[2 * j + 1]);
    *(int4*)&g_Gc[c][base] = *(int4*)o;
}

// ---------------------------------------------------------------------------
// K6: dot-v5 with H prefetch. grid (40 kchunks x 25 query-octets).
// ---------------------------------------------------------------------------
__global__ void __launch_bounds__(256) dot_kernel()
{
    const int kc   = blockIdx.x;            // 0..39
    const int q0   = blockIdx.y * 8;        // 0..192
    const int tid  = threadIdx.x;
    const int lane = tid & 31;
    const int warp = tid >> 5;
    const int kbase = kc * 4096 + tid * 16; // halves

    __half2 G[WAY][8];
#pragma unroll
    for (int c = 0; c < WAY; c++) {
        *(int4*)&G[c][0] = *(const int4*)&g_Gc[c][kbase];
        *(int4*)&G[c][4] = *(const int4*)&g_Gc[c][kbase + 8];
    }

    float acc[8][WAY];
#pragma unroll
    for (int qi = 0; qi < 8; qi++)
#pragma unroll
        for (int c = 0; c < WAY; c++) acc[qi][c] = 0.f;

    __half2 Hc[8];
    *(int4*)&Hc[0] = *(const int4*)(g_Hp[q0] + kbase);
    *(int4*)&Hc[4] = *(const int4*)(g_Hp[q0] + kbase + 8);

#pragma unroll
    for (int qi = 0; qi < 8; qi++) {
        __half2 Hn[8];
        if (qi < 7) {
            const __half* Hq = g_Hp[q0 + qi + 1] + kbase;
            *(int4*)&Hn[0] = *(const int4*)(Hq);
            *(int4*)&Hn[4] = *(const int4*)(Hq + 8);
        }
#pragma unroll
        for (int c = 0; c < WAY; c++) {
            __half2 a = __hmul2(G[c][0], Hc[0]);
#pragma unroll
            for (int j = 1; j < 8; j++) a = __hfma2(G[c][j], Hc[j], a);
            float2 f = __half22float2(a);
            acc[qi][c] = f.x + f.y;
        }
        if (qi < 7) {
#pragma unroll
            for (int j = 0; j < 8; j++) Hc[j] = Hn[j];
        }
    }

#pragma unroll
    for (int o = 16; o; o >>= 1)
#pragma unroll
        for (int qi = 0; qi < 8; qi++)
#pragma unroll
            for (int c = 0; c < WAY; c++)
                acc[qi][c] += __shfl_xor_sync(0xFFFFFFFFu, acc[qi][c], o);

    __shared__ float red[8][8][WAY];
    if (lane == 0)
#pragma unroll
        for (int qi = 0; qi < 8; qi++)
#pragma unroll
            for (int c = 0; c < WAY; c++) red[warp][qi][c] = acc[qi][c];
    __syncthreads();

    if (tid < 8 * WAY) {
        int qi = tid / WAY, c = tid % WAY;
        float s = 0.f;
#pragma unroll
        for (int w = 0; w < 8; w++) s += red[w][qi][c];
        atomicAdd(&g_S2[c][q0 + qi], s);
    }
}

// ---------------------------------------------------------------------------
// K7: logits (proven)
// ---------------------------------------------------------------------------
__global__ void logits_kernel(float* __restrict__ out)
{
    int warp = (blockIdx.x * blockDim.x + threadIdx.x) >> 5;
    int lane = threadIdx.x & 31;
    if (warp >= NQ) return;
    const int q = warp;

    float s1[WAY] = {0.f, 0.f, 0.f, 0.f, 0.f};
    const float* qb = g_bar[NS + q];
    for (int k = lane; k < DD; k += 32) {
        float qv = qb[k];
#pragma unroll
        for (int c = 0; c < WAY; c++) s1[c] += g_sbarsum[c][k] * qv;
    }
#pragma unroll
    for (int o = 16; o; o >>= 1)
#pragma unroll
        for (int c = 0; c < WAY; c++)
            s1[c] += __shfl_xor_sync(0xFFFFFFFFu, s1[c], o);

    if (lane < WAY) {
        int c = lane;
        float cnt = (float)g_cls_cnt[c];
        out[q * WAY + c] = -2.f * (float)(FF * FF) + (4.f * s1[c] - 2.f * g_S2[c][q]) / cnt;
    }
}

// ---------------------------------------------------------------------------
extern "C" void kernel_launch(void* const* d_in, const int* in_sizes, int n_in,
                              void* d_out, int out_size)
{
    const float*     sg  = (const float*)d_in[0];
    const float*     sl  = (const float*)d_in[1];
    const long long* lab = (const long long*)d_in[2];
    const float*     qg  = (const float*)d_in[3];
    const float*     ql  = (const float*)d_in[4];
    float*           out = (float*)d_out;

    const int smem = 2 * 2 * SLICE * 2;   // 2 stages x 2 slices = 87040 B
    static bool attr_set = false;
    if (!attr_set) {
        cudaFuncSetAttribute(gram_kernel, cudaFuncAttributeMaxDynamicSharedMemorySize, smem);
        attr_set = true;
    }

    const int rows = NITEM * FF;
    normalize_kernel<<<(rows * 32 + 255) / 256, 256>>>(sg, sl, qg, ql);
    rowsum_kernel<<<NITEM, 256>>>();
    prep_kernel<<<1, 512>>>(lab);
    gram_kernel<<<GGRID, 256, smem>>>();               // persistent, 2250 units
    classsum_kernel<<<dim3(KPACK / 2048, WAY), 256>>>();
    dot_kernel<<<dim3(40, 25), 256>>>();               // 1000 CTAs
    logits_kernel<<<(NQ * 32 + 255) / 256, 256>>>(out);
}